// round 1
// baseline (speedup 1.0000x reference)
#include <cuda_runtime.h>
#include <math.h>

#define BATCH 32
#define S 256
#define SS (S*S)
#define NPIX (BATCH*SS)

// t = tan(10/360*pi) = tan(5 deg)
#define TCONST 0.08748866352592400522f
#define EPSV 1e-7f
#define T_ALPHA 10.313708498984760f   // sqrt(128)-1
#define INV_GAMMA 0.45454545454545453f

// Normalized 1D gaussian weights (ksize=7, sigma=2), separable form of reference's 2D kernel
__device__ __constant__ float GW[7] = {
    0.07015932906686f, 0.13107487759864f, 0.19071282296459f,
    0.21610594073983f, 0.19071282296459f, 0.13107487759864f, 0.07015932906686f
};

struct BParams {
    float ldx, ldy, ldz;   // normalized light dir
    float sx, sy, sz;      // step = -light_d / S
    float la, lb;          // light_a, light_b
    float salpha;          // spec_alpha
    float sstr;            // spec_strength
    float mind;            // min depth (minus safety eps)
    float pad;
};

__device__ BParams g_params[BATCH];
__device__ float g_shadow[NPIX];
__device__ float g_blurh[NPIX];

// ---------------- per-batch scalar params ----------------
__global__ void setup_kernel(const float* __restrict__ netL,
                             const float* __restrict__ light) {
    int b = threadIdx.x;
    if (b >= BATCH) return;
    float lx = light[b*2+0];
    float ly = light[b*2+1];
    float nrm = sqrtf(lx*lx + ly*ly + 1.0f);
    float ldx = lx / nrm, ldy = ly / nrm, ldz = 1.0f / nrm;
    BParams p;
    p.ldx = ldx; p.ldy = ldy; p.ldz = ldz;
    p.sx = -ldx / (float)S;
    p.sy = -ldy / (float)S;
    p.sz = -ldz / (float)S;
    p.la = tanhf(netL[b*6+1]) * 0.5f + 0.5f;
    p.lb = tanhf(netL[b*6+2]) * 0.5f + 0.5f;
    float sa = tanhf(netL[b*6+0]);
    float t  = (sa * 0.5f + 0.5f) * T_ALPHA + 1.0f;
    p.salpha = t * t;
    p.sstr = (tanhf(netL[b*6+5]) * 0.5f + 0.5f) * 0.5f;
    p.mind = g_params[b].mind;  // preserved (written by min kernel which runs after; init value unused this launch)
    g_params[b] = p;
}

// ---------------- per-batch min depth ----------------
__global__ void mindepth_kernel(const float* __restrict__ depth) {
    __shared__ float sm[256];
    int b = blockIdx.x;
    const float* d = depth + b*SS;
    float m = 3.402823466e38f;
    for (int i = threadIdx.x; i < SS; i += 256)
        m = fminf(m, d[i]);
    sm[threadIdx.x] = m;
    __syncthreads();
    for (int o = 128; o > 0; o >>= 1) {
        if (threadIdx.x < o) sm[threadIdx.x] = fminf(sm[threadIdx.x], sm[threadIdx.x + o]);
        __syncthreads();
    }
    if (threadIdx.x == 0)
        g_params[b].mind = sm[0] - 1e-6f;   // safety margin for bilinear rounding
}

// ---------------- shadow ray-march ----------------
__global__ void __launch_bounds__(256)
shadow_kernel(const float* __restrict__ depth) {
    int idx = blockIdx.x * blockDim.x + threadIdx.x;
    if (idx >= NPIX) return;
    int b = idx >> 16;
    int p = idx & 0xFFFF;
    int i = p >> 8;
    int j = p & 255;

    BParams pr = g_params[b];
    const float* __restrict__ dimg = depth + b*SS;

    float d0 = __ldg(dimg + p);
    float cj = (-1.0f + (float)j * (2.0f/255.0f)) * TCONST;
    float ci = (-1.0f + (float)i * (2.0f/255.0f)) * TCONST;
    float px = cj * d0;
    float py = ci * d0;
    float pz = d0;

    bool sh = false;
    #pragma unroll 1
    for (int s = 0; s < S; s++) {
        px += pr.sx; py += pr.sy; pz += pr.sz;
        bool dead = sh || (pz <= pr.mind);
        if (!dead) {
            float gx = (px / pz) / TCONST;
            float gy = (py / pz) / TCONST;
            float x = (gx + 1.0f) * 128.0f - 0.5f;
            float y = (gy + 1.0f) * 128.0f - 0.5f;
            float x0f = floorf(x);
            float y0f = floorf(y);
            float wx = x - x0f;
            float wy = y - y0f;
            int xi = (int)x0f;
            int yi = (int)y0f;
            int x0 = min(max(xi,     0), 255);
            int x1 = min(max(xi + 1, 0), 255);
            int y0 = min(max(yi,     0), 255);
            int y1 = min(max(yi + 1, 0), 255);
            float v00 = __ldg(dimg + y0*256 + x0);
            float v01 = __ldg(dimg + y0*256 + x1);
            float v10 = __ldg(dimg + y1*256 + x0);
            float v11 = __ldg(dimg + y1*256 + x1);
            float sampled = v00*(1.0f-wx)*(1.0f-wy) + v01*wx*(1.0f-wy)
                          + v10*(1.0f-wx)*wy        + v11*wx*wy;
            sh = (sampled - pz) < 0.0f;
            dead = sh || (pz <= pr.mind);
        }
        if (__all_sync(0xFFFFFFFFu, dead)) break;
    }
    g_shadow[idx] = sh ? 1.0f : 0.0f;
}

// ---------------- horizontal blur pass (zero pad) ----------------
__global__ void __launch_bounds__(256)
blurh_kernel() {
    int idx = blockIdx.x * blockDim.x + threadIdx.x;
    if (idx >= NPIX) return;
    int j = idx & 255;
    int rowbase = idx - j;
    float acc = 0.0f;
    #pragma unroll
    for (int k = 0; k < 7; k++) {
        int jj = j + k - 3;
        if (jj >= 0 && jj < 256)
            acc += GW[k] * g_shadow[rowbase + jj];
    }
    g_blurh[idx] = acc;
}

// ---------------- final: vertical blur + full shading ----------------
__global__ void __launch_bounds__(256)
final_kernel(const float* __restrict__ netA,
             const float* __restrict__ normal,
             float* __restrict__ out) {
    int idx = blockIdx.x * blockDim.x + threadIdx.x;
    if (idx >= NPIX) return;
    int b = idx >> 16;
    int p = idx & 0xFFFF;
    int i = p >> 8;
    int j = p & 255;

    BParams pr = g_params[b];

    // vertical blur of horizontally-blurred shadow
    float ss = 0.0f;
    int base = b*SS + j;
    #pragma unroll
    for (int k = 0; k < 7; k++) {
        int ii = i + k - 3;
        if (ii >= 0 && ii < 256)
            ss += GW[k] * g_blurh[base + ii*256];
    }
    float sf = fminf(fmaxf(1.0f - ss, 0.1f), 1.0f);

    // normal
    int nb = b*3*SS + p;
    float nx = __ldg(normal + nb);
    float ny = __ldg(normal + nb + SS);
    float nz = __ldg(normal + nb + 2*SS);

    float cosq = nx*pr.ldx + ny*pr.ldy + nz*pr.ldz;
    float diffuse = fmaxf(cosq, 0.0f);
    float shading = pr.la + pr.lb * diffuse * sf;

    // view direction (with the [::-1,::-1] flip folded in: v = (-cj,-ci,1)/norm)
    float cj = (-1.0f + (float)j * (2.0f/255.0f)) * TCONST;
    float ci = (-1.0f + (float)i * (2.0f/255.0f)) * TCONST;
    float vx = -cj, vy = -ci, vz = 1.0f;
    float vn = sqrtf(vx*vx + vy*vy + vz*vz);
    vx /= vn; vy /= vn; vz /= vn;

    // reflect & specular
    float rx = 2.0f*cosq*nx - pr.ldx;
    float ry = 2.0f*cosq*ny - pr.ldy;
    float rz = 2.0f*cosq*nz - pr.ldz;
    float spec = fmaxf(vx*rx + vy*ry + vz*rz, 0.0f);
    float mask = (i >= 5 && i < 251 && j >= 5 && j < 251) ? 1.0f : 0.0f;
    spec = spec * ((cosq > 0.0f) ? 1.0f : 0.0f) * mask;
    float specc = fminf(fmaxf(spec, EPSV), 1.0f - EPSV);
    float spec_shading = powf(specc, pr.salpha);
    float spec_term = pr.sstr * pr.lb * spec_shading;

    int ab = b*5*SS + p;
    int ob = b*3*SS + p;
    #pragma unroll
    for (int c = 0; c < 3; c++) {
        float a = tanhf(__ldg(netA + ab + c*SS));
        float alb = powf(a * 0.5f + 0.5f, 2.2f);
        float v = alb * shading + spec_term;
        out[ob + c*SS] = powf(fmaxf(v, EPSV), INV_GAMMA);
    }
}

extern "C" void kernel_launch(void* const* d_in, const int* in_sizes, int n_in,
                              void* d_out, int out_size) {
    const float* netA   = (const float*)d_in[0];
    const float* netL   = (const float*)d_in[1];
    const float* normal = (const float*)d_in[2];
    const float* depth  = (const float*)d_in[3];
    const float* light  = (const float*)d_in[4];
    float* out = (float*)d_out;

    setup_kernel<<<1, 32>>>(netL, light);
    mindepth_kernel<<<BATCH, 256>>>(depth);
    shadow_kernel<<<NPIX/256, 256>>>(depth);
    blurh_kernel<<<NPIX/256, 256>>>();
    final_kernel<<<NPIX/256, 256>>>(netA, normal, out);
}

// round 3
// speedup vs baseline: 1.5045x; 1.5045x over previous
#include <cuda_runtime.h>
#include <math.h>

#define BATCH 32
#define S 256
#define SS (S*S)
#define NPIX (BATCH*SS)

#define TCONST 0.08748866352592400522f   // tan(5 deg)
#define EPSV 1e-7f
#define T_ALPHA 10.313708498984760f      // sqrt(128)-1
#define INV_GAMMA 0.45454545454545453f

__device__ __constant__ float GW[7] = {
    0.07015932906686f, 0.13107487759864f, 0.19071282296459f,
    0.21610594073983f, 0.19071282296459f, 0.13107487759864f, 0.07015932906686f
};

struct BParams {
    float ldx, ldy, ldz;     // normalized light dir
    float sxq, syq, sz;      // step in q-space (x,y) and z
    float la, lb;
    float salpha;
    float sstr;
    float mind;
    float pad;
};

__device__ BParams g_params[BATCH];
__device__ float g_shadow[NPIX];
__device__ float g_blurh[NPIX];

// ---------- fast math helpers (MUFU-based) ----------
__device__ __forceinline__ float fex2(float x){ float r; asm("ex2.approx.f32 %0,%1;":"=f"(r):"f"(x)); return r; }
__device__ __forceinline__ float flg2(float x){ float r; asm("lg2.approx.f32 %0,%1;":"=f"(r):"f"(x)); return r; }
__device__ __forceinline__ float frcp(float x){ float r; asm("rcp.approx.f32 %0,%1;":"=f"(r):"f"(x)); return r; }
__device__ __forceinline__ float frsq(float x){ float r; asm("rsqrt.approx.f32 %0,%1;":"=f"(r):"f"(x)); return r; }
__device__ __forceinline__ float fpow(float x, float y){ return fex2(y * flg2(x)); }
// tanh via exp2: tanh(x) = sign(x) * (1-t)/(1+t), t = exp(-2|x|) = 2^(-2|x|*log2e)
__device__ __forceinline__ float ftanh(float x){
    float ax = fabsf(x);
    float t = fex2(-2.8853900817779268f * ax);
    float r = (1.0f - t) * frcp(1.0f + t);
    return copysignf(r, x);
}

// ---------------- fused per-batch params + min depth ----------------
__global__ void setup_kernel(const float* __restrict__ netL,
                             const float* __restrict__ light,
                             const float* __restrict__ depth) {
    __shared__ float sm[256];
    int b = blockIdx.x;
    const float* d = depth + b*SS;
    float m = 3.402823466e38f;
    for (int i = threadIdx.x; i < SS; i += 256)
        m = fminf(m, d[i]);
    sm[threadIdx.x] = m;
    __syncthreads();
    for (int o = 128; o > 0; o >>= 1) {
        if (threadIdx.x < o) sm[threadIdx.x] = fminf(sm[threadIdx.x], sm[threadIdx.x + o]);
        __syncthreads();
    }
    if (threadIdx.x == 0) {
        float lx = light[b*2+0];
        float ly = light[b*2+1];
        float nrm = sqrtf(lx*lx + ly*ly + 1.0f);
        float ldx = lx / nrm, ldy = ly / nrm, ldz = 1.0f / nrm;
        BParams p;
        p.ldx = ldx; p.ldy = ldy; p.ldz = ldz;
        // step in q-space: q = p * 128/TCONST. step_p = -ld/S
        const float QS = 128.0f / TCONST;
        p.sxq = -ldx / (float)S * QS;
        p.syq = -ldy / (float)S * QS;
        p.sz  = -ldz / (float)S;
        p.la = tanhf(netL[b*6+1]) * 0.5f + 0.5f;
        p.lb = tanhf(netL[b*6+2]) * 0.5f + 0.5f;
        float sa = tanhf(netL[b*6+0]);
        float t  = (sa * 0.5f + 0.5f) * T_ALPHA + 1.0f;
        p.salpha = t * t;
        p.sstr = (tanhf(netL[b*6+5]) * 0.5f + 0.5f) * 0.5f;
        p.mind = sm[0] - 1e-6f;
        p.pad = 0.0f;
        g_params[b] = p;
    }
}

// ---------------- shadow ray-march ----------------
// q-space: x_img = qx/pz + 127.5, with qx0 = (j*(256/255)-128)*d0 (TCONST cancels)
__global__ void __launch_bounds__(256)
shadow_kernel(const float* __restrict__ depth) {
    int idx = blockIdx.x * blockDim.x + threadIdx.x;
    int b = idx >> 16;
    int p = idx & 0xFFFF;
    int i = p >> 8;
    int j = p & 255;

    BParams pr = g_params[b];
    const float* __restrict__ dimg = depth + b*SS;

    float d0 = __ldg(dimg + p);
    float qx = ((float)j * (256.0f/255.0f) - 128.0f) * d0;
    float qy = ((float)i * (256.0f/255.0f) - 128.0f) * d0;
    float pz = d0;

    bool sh = false;
    #pragma unroll 1
    for (int s = 0; s < S; s++) {
        qx += pr.sxq; qy += pr.syq; pz += pr.sz;
        bool dead = sh | (pz <= pr.mind);
        if (!dead) {
            float rz = frcp(pz);
            float x = fmaf(qx, rz, 127.5f);
            float y = fmaf(qy, rz, 127.5f);
            float x0f = floorf(x);
            float y0f = floorf(y);
            float wx = x - x0f;
            float wy = y - y0f;
            int xi = (int)x0f;
            int yi = (int)y0f;
            int x0 = min(max(xi,     0), 255);
            int x1 = min(max(xi + 1, 0), 255);
            int y0 = min(max(yi,     0), 255);
            int y1 = min(max(yi + 1, 0), 255);
            const float* r0 = dimg + y0*256;
            const float* r1 = dimg + y1*256;
            float v00 = __ldg(r0 + x0);
            float v01 = __ldg(r0 + x1);
            float v10 = __ldg(r1 + x0);
            float v11 = __ldg(r1 + x1);
            float top = v00 + wx*(v01 - v00);
            float bot = v10 + wx*(v11 - v10);
            float sampled = top + wy*(bot - top);
            sh = sampled < pz;
            dead = sh | (pz <= pr.mind);
        }
        if (__all_sync(0xFFFFFFFFu, dead)) break;
    }
    g_shadow[idx] = sh ? 1.0f : 0.0f;
}

// ---------------- horizontal blur (one row per block, smem) ----------------
__global__ void __launch_bounds__(256)
blurh_kernel() {
    __shared__ float row[256];
    int r = blockIdx.x;               // 0 .. BATCH*S-1
    int j = threadIdx.x;
    int base = r * 256;
    row[j] = g_shadow[base + j];
    __syncthreads();
    float acc = 0.0f;
    #pragma unroll
    for (int k = 0; k < 7; k++) {
        int jj = j + k - 3;
        if (jj >= 0 && jj < 256)
            acc += GW[k] * row[jj];
    }
    g_blurh[base + j] = acc;
}

// ---------------- final: vertical blur + full shading (fast math) ----------------
__global__ void __launch_bounds__(256)
final_kernel(const float* __restrict__ netA,
             const float* __restrict__ normal,
             float* __restrict__ out) {
    int idx = blockIdx.x * blockDim.x + threadIdx.x;
    int b = idx >> 16;
    int p = idx & 0xFFFF;
    int i = p >> 8;
    int j = p & 255;

    BParams pr = g_params[b];

    // vertical blur of horizontally-blurred shadow
    float ss = 0.0f;
    int base = b*SS + j;
    #pragma unroll
    for (int k = 0; k < 7; k++) {
        int ii = i + k - 3;
        if (ii >= 0 && ii < 256)
            ss += GW[k] * __ldg(&g_blurh[base + ii*256]);
    }
    float sf = fminf(fmaxf(1.0f - ss, 0.1f), 1.0f);

    // normal
    int nb = b*3*SS + p;
    float nx = __ldg(normal + nb);
    float ny = __ldg(normal + nb + SS);
    float nz = __ldg(normal + nb + 2*SS);

    float cosq = nx*pr.ldx + ny*pr.ldy + nz*pr.ldz;
    float diffuse = fmaxf(cosq, 0.0f);
    float shading = pr.la + pr.lb * diffuse * sf;

    // view direction (with [::-1,::-1] flip folded: v = (-cj,-ci,1)/norm)
    float cj = (-1.0f + (float)j * (2.0f/255.0f)) * TCONST;
    float ci = (-1.0f + (float)i * (2.0f/255.0f)) * TCONST;
    float vx = -cj, vy = -ci;
    float rn = frsq(fmaf(vx, vx, fmaf(vy, vy, 1.0f)));
    vx *= rn; vy *= rn; float vz = rn;

    // reflect & specular
    float rx = 2.0f*cosq*nx - pr.ldx;
    float ry = 2.0f*cosq*ny - pr.ldy;
    float rz = 2.0f*cosq*nz - pr.ldz;
    float spec = fmaxf(vx*rx + vy*ry + vz*rz, 0.0f);
    float mask = (i >= 5 && i < 251 && j >= 5 && j < 251) ? 1.0f : 0.0f;
    spec = spec * ((cosq > 0.0f) ? 1.0f : 0.0f) * mask;
    float specc = fminf(fmaxf(spec, EPSV), 1.0f - EPSV);
    float spec_shading = fpow(specc, pr.salpha);
    float spec_term = pr.sstr * pr.lb * spec_shading;

    int ab = b*5*SS + p;
    int ob = b*3*SS + p;
    #pragma unroll
    for (int c = 0; c < 3; c++) {
        float a = ftanh(__ldg(netA + ab + c*SS));
        float alb = fpow(fmaf(a, 0.5f, 0.5f), 2.2f);
        float v = alb * shading + spec_term;
        out[ob + c*SS] = fpow(fmaxf(v, EPSV), INV_GAMMA);
    }
}

extern "C" void kernel_launch(void* const* d_in, const int* in_sizes, int n_in,
                              void* d_out, int out_size) {
    const float* netA   = (const float*)d_in[0];
    const float* netL   = (const float*)d_in[1];
    const float* normal = (const float*)d_in[2];
    const float* depth  = (const float*)d_in[3];
    const float* light  = (const float*)d_in[4];
    float* out = (float*)d_out;

    setup_kernel<<<BATCH, 256>>>(netL, light, depth);
    shadow_kernel<<<NPIX/256, 256>>>(depth);
    blurh_kernel<<<BATCH*S, 256>>>();
    final_kernel<<<NPIX/256, 256>>>(netA, normal, out);
}

// round 5
// speedup vs baseline: 1.7077x; 1.1351x over previous
#include <cuda_runtime.h>
#include <math.h>

#define BATCH 32
#define S 256
#define SS (S*S)
#define NPIX (BATCH*SS)
#define PH1 24

#define TCONST 0.08748866352592400522f   // tan(5 deg)
#define EPSV 1e-7f
#define T_ALPHA 10.313708498984760f      // sqrt(128)-1
#define INV_GAMMA 0.45454545454545453f

__device__ __constant__ float GW[7] = {
    0.07015932906686f, 0.13107487759864f, 0.19071282296459f,
    0.21610594073983f, 0.19071282296459f, 0.13107487759864f, 0.07015932906686f
};

struct BParams {
    float ldx, ldy, ldz;
    float sxq, syq, sz;      // q-space steps (x,y) and z step
    float la, lb;
    float salpha;
    float sstr;
    float mind;
    float pad;
};

__device__ BParams g_params[BATCH];
__device__ unsigned g_minbits[BATCH];
__device__ int g_count;
__device__ int g_surv[NPIX];
__device__ float g_shadow[NPIX];
__device__ float g_blurh[NPIX];

// ---------- fast math helpers ----------
__device__ __forceinline__ float fex2(float x){ float r; asm("ex2.approx.f32 %0,%1;":"=f"(r):"f"(x)); return r; }
__device__ __forceinline__ float flg2(float x){ float r; asm("lg2.approx.f32 %0,%1;":"=f"(r):"f"(x)); return r; }
__device__ __forceinline__ float frcp(float x){ float r; asm("rcp.approx.f32 %0,%1;":"=f"(r):"f"(x)); return r; }
__device__ __forceinline__ float frsq(float x){ float r; asm("rsqrt.approx.f32 %0,%1;":"=f"(r):"f"(x)); return r; }
__device__ __forceinline__ float fpow(float x, float y){ return fex2(y * flg2(x)); }
__device__ __forceinline__ float ftanh(float x){
    float ax = fabsf(x);
    float t = fex2(-2.8853900817779268f * ax);
    float r = (1.0f - t) * frcp(1.0f + t);
    return copysignf(r, x);
}

// ---------------- reset ----------------
__global__ void reset_kernel() {
    int t = threadIdx.x;
    if (t < BATCH) g_minbits[t] = 0x7f7fffffu;
    if (t == 0) g_count = 0;
}

// ---------------- per-batch min depth (256 blocks, atomicMin on bits) ----------------
__global__ void minred_kernel(const float* __restrict__ depth) {
    __shared__ unsigned sm[256];
    int b = blockIdx.x >> 3;
    int chunk = blockIdx.x & 7;
    const float* d = depth + b*SS + chunk*(SS/8);
    float m = 3.402823466e38f;
    for (int i = threadIdx.x; i < SS/8; i += 256)
        m = fminf(m, d[i]);
    sm[threadIdx.x] = __float_as_uint(m);   // positive floats: uint order == float order
    __syncthreads();
    for (int o = 128; o > 0; o >>= 1) {
        if (threadIdx.x < o) sm[threadIdx.x] = min(sm[threadIdx.x], sm[threadIdx.x + o]);
        __syncthreads();
    }
    if (threadIdx.x == 0) atomicMin(&g_minbits[b], sm[0]);
}

// ---------------- per-batch scalar params ----------------
__global__ void params_kernel(const float* __restrict__ netL,
                              const float* __restrict__ light) {
    int b = threadIdx.x;
    if (b >= BATCH) return;
    float lx = light[b*2+0];
    float ly = light[b*2+1];
    float nrm = sqrtf(lx*lx + ly*ly + 1.0f);
    float ldx = lx / nrm, ldy = ly / nrm, ldz = 1.0f / nrm;
    BParams p;
    p.ldx = ldx; p.ldy = ldy; p.ldz = ldz;
    const float QS = 128.0f / TCONST;
    p.sxq = -ldx / (float)S * QS;
    p.syq = -ldy / (float)S * QS;
    p.sz  = -ldz / (float)S;
    p.la = tanhf(netL[b*6+1]) * 0.5f + 0.5f;
    p.lb = tanhf(netL[b*6+2]) * 0.5f + 0.5f;
    float sa = tanhf(netL[b*6+0]);
    float t  = (sa * 0.5f + 0.5f) * T_ALPHA + 1.0f;
    p.salpha = t * t;
    p.sstr = (tanhf(netL[b*6+5]) * 0.5f + 0.5f) * 0.5f;
    p.mind = __uint_as_float(g_minbits[b]) - 1e-6f;
    p.pad = 0.0f;
    g_params[b] = p;
}

// trip count: number of steps with pz > mind (+1 safety; extra steps provably can't shadow)
__device__ __forceinline__ int trip_count(float d0, float mind, float sz) {
    float f = (mind - d0) / sz;                    // >= 0 (both numerator<=0, sz<0)
    return min(S, (int)f + 1);
}

__device__ __forceinline__ bool sample_step(const float* __restrict__ dimg,
                                            float qx, float qy, float rz, float pz) {
    float x = fmaf(qx, rz, 127.5f);
    float y = fmaf(qy, rz, 127.5f);
    float x0f = floorf(x);
    float y0f = floorf(y);
    float wx = x - x0f;
    float wy = y - y0f;
    int xi = (int)x0f;
    int yi = (int)y0f;
    int x0 = min(max(xi,     0), 255);
    int x1 = min(max(xi + 1, 0), 255);
    int y0 = min(max(yi,     0), 255);
    int y1 = min(max(yi + 1, 0), 255);
    const float* r0 = dimg + y0*256;
    const float* r1 = dimg + y1*256;
    float v00 = __ldg(r0 + x0);
    float v01 = __ldg(r0 + x1);
    float v10 = __ldg(r1 + x0);
    float v11 = __ldg(r1 + x1);
    float top = v00 + wx*(v01 - v00);
    float bot = v10 + wx*(v11 - v10);
    float sampled = top + wy*(bot - top);
    return sampled < pz;
}

// ---------------- shadow phase 1: first PH1 steps + survivor compaction ----------------
__global__ void __launch_bounds__(256)
shadow_p1_kernel(const float* __restrict__ depth) {
    int idx = blockIdx.x * blockDim.x + threadIdx.x;
    int b = idx >> 16;
    int p = idx & 0xFFFF;
    int i = p >> 8;
    int j = p & 255;

    BParams pr = g_params[b];
    const float* __restrict__ dimg = depth + b*SS;

    float d0 = __ldg(dimg + p);
    float qx = ((float)j * (256.0f/255.0f) - 128.0f) * d0;
    float qy = ((float)i * (256.0f/255.0f) - 128.0f) * d0;
    float pz = d0;
    int nst = trip_count(d0, pr.mind, pr.sz);

    bool sh = false;
    #pragma unroll 1
    for (int s = 0; s < PH1; s++) {
        bool live = (!sh) & (s < nst);
        if (live) {
            qx += pr.sxq; qy += pr.syq; pz += pr.sz;
            sh = sample_step(dimg, qx, qy, frcp(pz), pz);
        }
        if (__all_sync(0xFFFFFFFFu, sh | ((s+1) >= nst))) break;
    }

    bool alive = (!sh) && (nst > PH1);
    unsigned mask = __ballot_sync(0xFFFFFFFFu, alive);
    if (alive) {
        int lane = threadIdx.x & 31;
        int leader = __ffs(mask) - 1;
        int pos = 0;
        if (lane == leader) pos = atomicAdd(&g_count, __popc(mask));
        pos = __shfl_sync(0xFFFFFFFFu, pos, leader);
        g_surv[pos + __popc(mask & ((1u << lane) - 1u))] = idx;
    } else {
        g_shadow[idx] = sh ? 1.0f : 0.0f;
    }
}

// ---------------- shadow phase 2: densely packed survivors, march to completion ----------------
__global__ void __launch_bounds__(256)
shadow_p2_kernel(const float* __restrict__ depth) {
    int total = g_count;
    int lane = threadIdx.x & 31;
    int gwarp = (blockIdx.x * blockDim.x + threadIdx.x) >> 5;
    int nwarps = (gridDim.x * blockDim.x) >> 5;

    for (int base = gwarp * 32; base < total; base += nwarps * 32) {
        int k = base + lane;
        bool valid = (k < total);
        int idx = valid ? g_surv[k] : g_surv[total - 1];
        int b = idx >> 16;
        int p = idx & 0xFFFF;
        int i = p >> 8;
        int j = p & 255;

        BParams pr = g_params[b];
        const float* __restrict__ dimg = depth + b*SS;
        float d0 = __ldg(dimg + p);
        // reconstruct state at s = PH1 (survivors completed exactly PH1 updates)
        float qx = fmaf((float)PH1, pr.sxq, ((float)j * (256.0f/255.0f) - 128.0f) * d0);
        float qy = fmaf((float)PH1, pr.syq, ((float)i * (256.0f/255.0f) - 128.0f) * d0);
        float pz = fmaf((float)PH1, pr.sz, d0);
        int nst = valid ? trip_count(d0, pr.mind, pr.sz) : 0;

        bool sh = false;
        #pragma unroll 1
        for (int s = PH1; s < S; s++) {
            bool live = (!sh) & (s < nst);
            if (live) {
                qx += pr.sxq; qy += pr.syq; pz += pr.sz;
                sh = sample_step(dimg, qx, qy, frcp(pz), pz);
            }
            if (__all_sync(0xFFFFFFFFu, sh | ((s+1) >= nst))) break;
        }
        if (valid) g_shadow[idx] = sh ? 1.0f : 0.0f;
    }
}

// ---------------- horizontal blur (one row per block, smem) ----------------
__global__ void __launch_bounds__(256)
blurh_kernel() {
    __shared__ float row[256];
    int r = blockIdx.x;
    int j = threadIdx.x;
    int base = r * 256;
    row[j] = g_shadow[base + j];
    __syncthreads();
    float acc = 0.0f;
    #pragma unroll
    for (int k = 0; k < 7; k++) {
        int jj = j + k - 3;
        if (jj >= 0 && jj < 256)
            acc += GW[k] * row[jj];
    }
    g_blurh[base + j] = acc;
}

// ---------------- final: vertical blur + full shading ----------------
__global__ void __launch_bounds__(256)
final_kernel(const float* __restrict__ netA,
             const float* __restrict__ normal,
             float* __restrict__ out) {
    int idx = blockIdx.x * blockDim.x + threadIdx.x;
    int b = idx >> 16;
    int p = idx & 0xFFFF;
    int i = p >> 8;
    int j = p & 255;

    BParams pr = g_params[b];

    float ss = 0.0f;
    int base = b*SS + j;
    #pragma unroll
    for (int k = 0; k < 7; k++) {
        int ii = i + k - 3;
        if (ii >= 0 && ii < 256)
            ss += GW[k] * __ldg(&g_blurh[base + ii*256]);
    }
    float sf = fminf(fmaxf(1.0f - ss, 0.1f), 1.0f);

    int nb = b*3*SS + p;
    float nx = __ldg(normal + nb);
    float ny = __ldg(normal + nb + SS);
    float nz = __ldg(normal + nb + 2*SS);

    float cosq = nx*pr.ldx + ny*pr.ldy + nz*pr.ldz;
    float diffuse = fmaxf(cosq, 0.0f);
    float shading = pr.la + pr.lb * diffuse * sf;

    float cj = (-1.0f + (float)j * (2.0f/255.0f)) * TCONST;
    float ci = (-1.0f + (float)i * (2.0f/255.0f)) * TCONST;
    float vx = -cj, vy = -ci;
    float rn = frsq(fmaf(vx, vx, fmaf(vy, vy, 1.0f)));
    vx *= rn; vy *= rn; float vz = rn;

    float rx = 2.0f*cosq*nx - pr.ldx;
    float ry = 2.0f*cosq*ny - pr.ldy;
    float rz = 2.0f*cosq*nz - pr.ldz;
    float spec = fmaxf(vx*rx + vy*ry + vz*rz, 0.0f);
    float mask = (i >= 5 && i < 251 && j >= 5 && j < 251) ? 1.0f : 0.0f;
    spec = spec * ((cosq > 0.0f) ? 1.0f : 0.0f) * mask;
    float specc = fminf(fmaxf(spec, EPSV), 1.0f - EPSV);
    float spec_shading = fpow(specc, pr.salpha);
    float spec_term = pr.sstr * pr.lb * spec_shading;

    int ab = b*5*SS + p;
    int ob = b*3*SS + p;
    #pragma unroll
    for (int c = 0; c < 3; c++) {
        float a = ftanh(__ldg(netA + ab + c*SS));
        float alb = fpow(fmaf(a, 0.5f, 0.5f), 2.2f);
        float v = alb * shading + spec_term;
        out[ob + c*SS] = fpow(fmaxf(v, EPSV), INV_GAMMA);
    }
}

extern "C" void kernel_launch(void* const* d_in, const int* in_sizes, int n_in,
                              void* d_out, int out_size) {
    const float* netA   = (const float*)d_in[0];
    const float* netL   = (const float*)d_in[1];
    const float* normal = (const float*)d_in[2];
    const float* depth  = (const float*)d_in[3];
    const float* light  = (const float*)d_in[4];
    float* out = (float*)d_out;

    reset_kernel<<<1, 64>>>();
    minred_kernel<<<BATCH*8, 256>>>(depth);
    params_kernel<<<1, 32>>>(netL, light);
    shadow_p1_kernel<<<NPIX/256, 256>>>(depth);
    shadow_p2_kernel<<<1024, 256>>>(depth);
    blurh_kernel<<<BATCH*S, 256>>>();
    final_kernel<<<NPIX/256, 256>>>(netA, normal, out);
}

// round 6
// speedup vs baseline: 1.7206x; 1.0076x over previous
#include <cuda_runtime.h>
#include <math.h>

#define BATCH 32
#define S 256
#define SS (S*S)
#define NPIX (BATCH*SS)
#define PH1 8

#define TCONST 0.08748866352592400522f   // tan(5 deg)
#define EPSV 1e-7f
#define T_ALPHA 10.313708498984760f      // sqrt(128)-1
#define INV_GAMMA 0.45454545454545453f

__device__ __constant__ float GW[7] = {
    0.07015932906686f, 0.13107487759864f, 0.19071282296459f,
    0.21610594073983f, 0.19071282296459f, 0.13107487759864f, 0.07015932906686f
};

struct BParams {
    float ldx, ldy, ldz;
    float sxq, syq, sz;      // q-space steps (x,y) and z step
    float la, lb;
    float salpha;
    float sstr;
    float mind;
    float pad;
};

__device__ BParams g_params[BATCH];
__device__ unsigned g_minbits[BATCH];
__device__ int g_count;
__device__ int g_surv[NPIX];
__device__ float g_shadow[NPIX];
__device__ float g_blurh[NPIX];

// ---------- fast math helpers ----------
__device__ __forceinline__ float fex2(float x){ float r; asm("ex2.approx.f32 %0,%1;":"=f"(r):"f"(x)); return r; }
__device__ __forceinline__ float flg2(float x){ float r; asm("lg2.approx.f32 %0,%1;":"=f"(r):"f"(x)); return r; }
__device__ __forceinline__ float frcp(float x){ float r; asm("rcp.approx.f32 %0,%1;":"=f"(r):"f"(x)); return r; }
__device__ __forceinline__ float frsq(float x){ float r; asm("rsqrt.approx.f32 %0,%1;":"=f"(r):"f"(x)); return r; }
__device__ __forceinline__ float fpow(float x, float y){ return fex2(y * flg2(x)); }
__device__ __forceinline__ float ftanh(float x){
    float ax = fabsf(x);
    float t = fex2(-2.8853900817779268f * ax);
    float r = (1.0f - t) * frcp(1.0f + t);
    return copysignf(r, x);
}

// ---------------- reset ----------------
__global__ void reset_kernel() {
    int t = threadIdx.x;
    if (t < BATCH) g_minbits[t] = 0x7f7fffffu;
    if (t == 0) g_count = 0;
}

// ---------------- per-batch min depth ----------------
__global__ void minred_kernel(const float* __restrict__ depth) {
    __shared__ unsigned sm[256];
    int b = blockIdx.x >> 3;
    int chunk = blockIdx.x & 7;
    const float* d = depth + b*SS + chunk*(SS/8);
    float m = 3.402823466e38f;
    for (int i = threadIdx.x; i < SS/8; i += 256)
        m = fminf(m, d[i]);
    sm[threadIdx.x] = __float_as_uint(m);   // positive floats: uint order == float order
    __syncthreads();
    for (int o = 128; o > 0; o >>= 1) {
        if (threadIdx.x < o) sm[threadIdx.x] = min(sm[threadIdx.x], sm[threadIdx.x + o]);
        __syncthreads();
    }
    if (threadIdx.x == 0) atomicMin(&g_minbits[b], sm[0]);
}

// ---------------- per-batch scalar params ----------------
__global__ void params_kernel(const float* __restrict__ netL,
                              const float* __restrict__ light) {
    int b = threadIdx.x;
    if (b >= BATCH) return;
    float lx = light[b*2+0];
    float ly = light[b*2+1];
    float nrm = sqrtf(lx*lx + ly*ly + 1.0f);
    float ldx = lx / nrm, ldy = ly / nrm, ldz = 1.0f / nrm;
    BParams p;
    p.ldx = ldx; p.ldy = ldy; p.ldz = ldz;
    const float QS = 128.0f / TCONST;
    p.sxq = -ldx / (float)S * QS;
    p.syq = -ldy / (float)S * QS;
    p.sz  = -ldz / (float)S;
    p.la = tanhf(netL[b*6+1]) * 0.5f + 0.5f;
    p.lb = tanhf(netL[b*6+2]) * 0.5f + 0.5f;
    float sa = tanhf(netL[b*6+0]);
    float t  = (sa * 0.5f + 0.5f) * T_ALPHA + 1.0f;
    p.salpha = t * t;
    p.sstr = (tanhf(netL[b*6+5]) * 0.5f + 0.5f) * 0.5f;
    p.mind = __uint_as_float(g_minbits[b]) - 1e-6f;
    p.pad = 0.0f;
    g_params[b] = p;
}

// trip count: number of steps with pz > mind (+1 safety; extra steps provably can't shadow)
__device__ __forceinline__ int trip_count(float d0, float mind, float sz) {
    float f = (mind - d0) / sz;                    // >= 0
    return min(S, (int)f + 1);
}

// bilinear sample; coords pre-clamped (reference's independent x0/x1 clamping is
// value-equivalent to clamping x first: out-of-range collapses to the border pixel)
__device__ __forceinline__ float bilin(const float* __restrict__ dimg,
                                       float x, float y) {
    float xc = fminf(fmaxf(x, 0.0f), 255.0f);
    float yc = fminf(fmaxf(y, 0.0f), 255.0f);
    int x0 = (int)xc;
    int y0 = (int)yc;
    float wx = xc - (float)x0;
    float wy = yc - (float)y0;
    int x1 = min(x0 + 1, 255);
    int y1 = min(y0 + 1, 255);
    const float* r0 = dimg + y0*256;
    const float* r1 = dimg + y1*256;
    float v00 = __ldg(r0 + x0);
    float v01 = __ldg(r0 + x1);
    float v10 = __ldg(r1 + x0);
    float v11 = __ldg(r1 + x1);
    float top = v00 + wx*(v01 - v00);
    float bot = v10 + wx*(v11 - v10);
    return top + wy*(bot - top);
}

// ---------------- shadow phase 1: first PH1 steps + survivor compaction ----------------
__global__ void __launch_bounds__(256)
shadow_p1_kernel(const float* __restrict__ depth) {
    int idx = blockIdx.x * blockDim.x + threadIdx.x;
    int b = idx >> 16;
    int p = idx & 0xFFFF;
    int i = p >> 8;
    int j = p & 255;

    BParams pr = g_params[b];
    const float* __restrict__ dimg = depth + b*SS;

    float d0 = __ldg(dimg + p);
    float qx = ((float)j * (256.0f/255.0f) - 128.0f) * d0;
    float qy = ((float)i * (256.0f/255.0f) - 128.0f) * d0;
    float pz = d0;
    int nst = trip_count(d0, pr.mind, pr.sz);

    bool sh = false;
    int lim = min(nst, PH1);
    #pragma unroll 1
    for (int s = 0; s < lim; s++) {
        qx += pr.sxq; qy += pr.syq; pz += pr.sz;
        float rz = frcp(pz);
        float x = fmaf(qx, rz, 127.5f);
        float y = fmaf(qy, rz, 127.5f);
        if (bilin(dimg, x, y) < pz) { sh = true; break; }
    }

    bool alive = (!sh) && (nst > PH1);
    unsigned mask = __ballot_sync(0xFFFFFFFFu, alive);
    if (alive) {
        int lane = threadIdx.x & 31;
        int leader = __ffs(mask) - 1;
        int pos = 0;
        if (lane == leader) pos = atomicAdd(&g_count, __popc(mask));
        pos = __shfl_sync(0xFFFFFFFFu, pos, leader);
        g_surv[pos + __popc(mask & ((1u << lane) - 1u))] = idx;
    } else {
        g_shadow[idx] = sh ? 1.0f : 0.0f;
    }
}

// ---------------- shadow phase 2: dense survivors, march to completion ----------------
// Adds frozen-corner exit: x(s)=qx/pz and y(s)=qy/pz are MONOTONE along the ray
// (d/ds numerator sxq*pz - qx*sz is ray-constant), so once both coords are past
// the image border in their motion direction, the sample is frozen at a corner c.
// Then c >= pz now and pz strictly decreasing => never shadows => break.
__global__ void __launch_bounds__(256)
shadow_p2_kernel(const float* __restrict__ depth) {
    int total = g_count;
    int lane = threadIdx.x & 31;
    int gwarp = (blockIdx.x * blockDim.x + threadIdx.x) >> 5;
    int nwarps = (gridDim.x * blockDim.x) >> 5;

    for (int base = gwarp * 32; base < total; base += nwarps * 32) {
        int k = base + lane;
        bool valid = (k < total);
        int idx = valid ? g_surv[k] : g_surv[total - 1];
        int b = idx >> 16;
        int p = idx & 0xFFFF;
        int i = p >> 8;
        int j = p & 255;

        BParams pr = g_params[b];
        const float* __restrict__ dimg = depth + b*SS;
        float d0 = __ldg(dimg + p);
        // reconstruct state at s = PH1
        float qx = fmaf((float)PH1, pr.sxq, ((float)j * (256.0f/255.0f) - 128.0f) * d0);
        float qy = fmaf((float)PH1, pr.syq, ((float)i * (256.0f/255.0f) - 128.0f) * d0);
        float pz = fmaf((float)PH1, pr.sz, d0);
        int nst = valid ? trip_count(d0, pr.mind, pr.sz) : 0;

        // ray-constant coordinate motion signs
        float cx = pr.sxq * pz - qx * pr.sz;
        float cy = pr.syq * pz - qy * pr.sz;

        bool sh = false;
        #pragma unroll 1
        for (int s = PH1; s < nst; s++) {
            qx += pr.sxq; qy += pr.syq; pz += pr.sz;
            float rz = frcp(pz);
            float x = fmaf(qx, rz, 127.5f);
            float y = fmaf(qy, rz, 127.5f);
            if (bilin(dimg, x, y) < pz) { sh = true; break; }
            bool xout = (cx > 0.0f) ? (x >= 255.0f) : ((cx < 0.0f) ? (x <= 0.0f) : false);
            bool yout = (cy > 0.0f) ? (y >= 255.0f) : ((cy < 0.0f) ? (y <= 0.0f) : false);
            if (xout && yout) break;   // frozen corner, c >= pz, pz decreasing -> never shadows
        }
        if (valid) g_shadow[idx] = sh ? 1.0f : 0.0f;
    }
}

// ---------------- horizontal blur (one row per block, smem) ----------------
__global__ void __launch_bounds__(256)
blurh_kernel() {
    __shared__ float row[256];
    int r = blockIdx.x;
    int j = threadIdx.x;
    int base = r * 256;
    row[j] = g_shadow[base + j];
    __syncthreads();
    float acc = 0.0f;
    #pragma unroll
    for (int k = 0; k < 7; k++) {
        int jj = j + k - 3;
        if (jj >= 0 && jj < 256)
            acc += GW[k] * row[jj];
    }
    g_blurh[base + j] = acc;
}

// ---------------- final: vertical blur + full shading ----------------
__global__ void __launch_bounds__(256)
final_kernel(const float* __restrict__ netA,
             const float* __restrict__ normal,
             float* __restrict__ out) {
    int idx = blockIdx.x * blockDim.x + threadIdx.x;
    int b = idx >> 16;
    int p = idx & 0xFFFF;
    int i = p >> 8;
    int j = p & 255;

    BParams pr = g_params[b];

    float ss = 0.0f;
    int base = b*SS + j;
    #pragma unroll
    for (int k = 0; k < 7; k++) {
        int ii = i + k - 3;
        if (ii >= 0 && ii < 256)
            ss += GW[k] * __ldg(&g_blurh[base + ii*256]);
    }
    float sf = fminf(fmaxf(1.0f - ss, 0.1f), 1.0f);

    int nb = b*3*SS + p;
    float nx = __ldg(normal + nb);
    float ny = __ldg(normal + nb + SS);
    float nz = __ldg(normal + nb + 2*SS);

    float cosq = nx*pr.ldx + ny*pr.ldy + nz*pr.ldz;
    float diffuse = fmaxf(cosq, 0.0f);
    float shading = pr.la + pr.lb * diffuse * sf;

    float cj = (-1.0f + (float)j * (2.0f/255.0f)) * TCONST;
    float ci = (-1.0f + (float)i * (2.0f/255.0f)) * TCONST;
    float vx = -cj, vy = -ci;
    float rn = frsq(fmaf(vx, vx, fmaf(vy, vy, 1.0f)));
    vx *= rn; vy *= rn; float vz = rn;

    float rx = 2.0f*cosq*nx - pr.ldx;
    float ry = 2.0f*cosq*ny - pr.ldy;
    float rz = 2.0f*cosq*nz - pr.ldz;
    float spec = fmaxf(vx*rx + vy*ry + vz*rz, 0.0f);
    float mask = (i >= 5 && i < 251 && j >= 5 && j < 251) ? 1.0f : 0.0f;
    spec = spec * ((cosq > 0.0f) ? 1.0f : 0.0f) * mask;
    float specc = fminf(fmaxf(spec, EPSV), 1.0f - EPSV);
    float spec_shading = fpow(specc, pr.salpha);
    float spec_term = pr.sstr * pr.lb * spec_shading;

    int ab = b*5*SS + p;
    int ob = b*3*SS + p;
    #pragma unroll
    for (int c = 0; c < 3; c++) {
        float a = ftanh(__ldg(netA + ab + c*SS));
        float alb = fpow(fmaf(a, 0.5f, 0.5f), 2.2f);
        float v = alb * shading + spec_term;
        out[ob + c*SS] = fpow(fmaxf(v, EPSV), INV_GAMMA);
    }
}

extern "C" void kernel_launch(void* const* d_in, const int* in_sizes, int n_in,
                              void* d_out, int out_size) {
    const float* netA   = (const float*)d_in[0];
    const float* netL   = (const float*)d_in[1];
    const float* normal = (const float*)d_in[2];
    const float* depth  = (const float*)d_in[3];
    const float* light  = (const float*)d_in[4];
    float* out = (float*)d_out;

    reset_kernel<<<1, 64>>>();
    minred_kernel<<<BATCH*8, 256>>>(depth);
    params_kernel<<<1, 32>>>(netL, light);
    shadow_p1_kernel<<<NPIX/256, 256>>>(depth);
    shadow_p2_kernel<<<2048, 256>>>(depth);
    blurh_kernel<<<BATCH*S, 256>>>();
    final_kernel<<<NPIX/256, 256>>>(netA, normal, out);
}

// round 7
// speedup vs baseline: 2.3717x; 1.3784x over previous
#include <cuda_runtime.h>
#include <math.h>

#define BATCH 32
#define S 256
#define SS (S*S)
#define NPIX (BATCH*SS)
#define PH1 8

#define TCONST 0.08748866352592400522f   // tan(5 deg)
#define EPSV 1e-7f
#define T_ALPHA 10.313708498984760f      // sqrt(128)-1
#define INV_GAMMA 0.45454545454545453f

__device__ __constant__ float GW[7] = {
    0.07015932906686f, 0.13107487759864f, 0.19071282296459f,
    0.21610594073983f, 0.19071282296459f, 0.13107487759864f, 0.07015932906686f
};

struct BParams {
    float ldx, ldy, ldz;
    float sxq, syq, sz;
    float la, lb;
    float salpha;
    float sstr;
    float mind;
    float pad;
};

__device__ BParams g_params[BATCH];
__device__ unsigned g_minbits[BATCH];
__device__ int g_count;
__device__ int g_surv[NPIX];
__device__ float g_shadow[NPIX];
__device__ float g_blurh[NPIX];
__device__ float4 g_quad[NPIX];          // 32MB: 4 bilinear taps per texel, border-clamped

// ---------- fast math helpers ----------
__device__ __forceinline__ float fex2(float x){ float r; asm("ex2.approx.f32 %0,%1;":"=f"(r):"f"(x)); return r; }
__device__ __forceinline__ float flg2(float x){ float r; asm("lg2.approx.f32 %0,%1;":"=f"(r):"f"(x)); return r; }
__device__ __forceinline__ float frcp(float x){ float r; asm("rcp.approx.f32 %0,%1;":"=f"(r):"f"(x)); return r; }
__device__ __forceinline__ float frsq(float x){ float r; asm("rsqrt.approx.f32 %0,%1;":"=f"(r):"f"(x)); return r; }
__device__ __forceinline__ float fpow(float x, float y){ return fex2(y * flg2(x)); }
__device__ __forceinline__ float ftanh(float x){
    float ax = fabsf(x);
    float t = fex2(-2.8853900817779268f * ax);
    float r = (1.0f - t) * frcp(1.0f + t);
    return copysignf(r, x);
}

// ---------------- reset ----------------
__global__ void reset_kernel() {
    int t = threadIdx.x;
    if (t < BATCH) g_minbits[t] = 0x7f7fffffu;
    if (t == 0) g_count = 0;
}

// ---------------- build quad map + per-batch min (fused) ----------------
__global__ void __launch_bounds__(256)
qbuild_kernel(const float* __restrict__ depth) {
    __shared__ unsigned sm[256];
    int idx = blockIdx.x * blockDim.x + threadIdx.x;   // NPIX threads
    int b = idx >> 16;
    int p = idx & 0xFFFF;
    int y = p >> 8;
    int x = p & 255;
    const float* dimg = depth + b*SS;
    int x1 = min(x + 1, 255);
    int y1 = min(y + 1, 255);
    float v00 = __ldg(dimg + y*256 + x);
    float v01 = __ldg(dimg + y*256 + x1);
    float v10 = __ldg(dimg + y1*256 + x);
    float v11 = __ldg(dimg + y1*256 + x1);
    g_quad[idx] = make_float4(v00, v01, v10, v11);

    // block min reduction (each block is within one batch: 256 | SS)
    sm[threadIdx.x] = __float_as_uint(v00);
    __syncthreads();
    for (int o = 128; o > 0; o >>= 1) {
        if (threadIdx.x < o) sm[threadIdx.x] = min(sm[threadIdx.x], sm[threadIdx.x + o]);
        __syncthreads();
    }
    if (threadIdx.x == 0) atomicMin(&g_minbits[b], sm[0]);
}

// ---------------- per-batch scalar params ----------------
__global__ void params_kernel(const float* __restrict__ netL,
                              const float* __restrict__ light) {
    int b = threadIdx.x;
    if (b >= BATCH) return;
    float lx = light[b*2+0];
    float ly = light[b*2+1];
    float nrm = sqrtf(lx*lx + ly*ly + 1.0f);
    float ldx = lx / nrm, ldy = ly / nrm, ldz = 1.0f / nrm;
    BParams p;
    p.ldx = ldx; p.ldy = ldy; p.ldz = ldz;
    const float QS = 128.0f / TCONST;
    p.sxq = -ldx / (float)S * QS;
    p.syq = -ldy / (float)S * QS;
    p.sz  = -ldz / (float)S;
    p.la = tanhf(netL[b*6+1]) * 0.5f + 0.5f;
    p.lb = tanhf(netL[b*6+2]) * 0.5f + 0.5f;
    float sa = tanhf(netL[b*6+0]);
    float t  = (sa * 0.5f + 0.5f) * T_ALPHA + 1.0f;
    p.salpha = t * t;
    p.sstr = (tanhf(netL[b*6+5]) * 0.5f + 0.5f) * 0.5f;
    p.mind = __uint_as_float(g_minbits[b]) - 1e-6f;
    p.pad = 0.0f;
    g_params[b] = p;
}

__device__ __forceinline__ int trip_count(float d0, float mind, float sz) {
    float f = (mind - d0) / sz;
    return min(S, (int)f + 1);
}

// single-LDG bilinear via quad map (coords pre-clamped; identical values to reference)
__device__ __forceinline__ float bilinq(const float4* __restrict__ qimg,
                                        float x, float y) {
    float xc = fminf(fmaxf(x, 0.0f), 255.0f);
    float yc = fminf(fmaxf(y, 0.0f), 255.0f);
    int x0 = (int)xc;
    int y0 = (int)yc;
    float wx = xc - (float)x0;
    float wy = yc - (float)y0;
    float4 q = __ldg(qimg + y0*256 + x0);
    float top = q.x + wx*(q.y - q.x);
    float bot = q.z + wx*(q.w - q.z);
    return top + wy*(bot - top);
}

// ---------------- shadow phase 1 ----------------
__global__ void __launch_bounds__(256)
shadow_p1_kernel(const float* __restrict__ depth) {
    int idx = blockIdx.x * blockDim.x + threadIdx.x;
    int b = idx >> 16;
    int p = idx & 0xFFFF;
    int i = p >> 8;
    int j = p & 255;

    BParams pr = g_params[b];
    const float4* __restrict__ qimg = g_quad + b*SS;

    float d0 = __ldg(depth + b*SS + p);
    float qx = ((float)j * (256.0f/255.0f) - 128.0f) * d0;
    float qy = ((float)i * (256.0f/255.0f) - 128.0f) * d0;
    float pz = d0;
    int nst = trip_count(d0, pr.mind, pr.sz);

    bool sh = false;
    int lim = min(nst, PH1);
    #pragma unroll 1
    for (int s = 0; s < lim; s++) {
        qx += pr.sxq; qy += pr.syq; pz += pr.sz;
        float rz = frcp(pz);
        float x = fmaf(qx, rz, 127.5f);
        float y = fmaf(qy, rz, 127.5f);
        if (bilinq(qimg, x, y) < pz) { sh = true; break; }
    }

    bool alive = (!sh) && (nst > PH1);
    unsigned mask = __ballot_sync(0xFFFFFFFFu, alive);
    if (alive) {
        int lane = threadIdx.x & 31;
        int leader = __ffs(mask) - 1;
        int pos = 0;
        if (lane == leader) pos = atomicAdd(&g_count, __popc(mask));
        pos = __shfl_sync(0xFFFFFFFFu, pos, leader);
        g_surv[pos + __popc(mask & ((1u << lane) - 1u))] = idx;
    } else {
        g_shadow[idx] = sh ? 1.0f : 0.0f;
    }
}

// ---------------- shadow phase 2 (dense survivors + frozen-corner exit) ----------------
__global__ void __launch_bounds__(256)
shadow_p2_kernel(const float* __restrict__ depth) {
    int total = g_count;
    int lane = threadIdx.x & 31;
    int gwarp = (blockIdx.x * blockDim.x + threadIdx.x) >> 5;
    int nwarps = (gridDim.x * blockDim.x) >> 5;

    for (int base = gwarp * 32; base < total; base += nwarps * 32) {
        int k = base + lane;
        bool valid = (k < total);
        int idx = valid ? g_surv[k] : g_surv[total - 1];
        int b = idx >> 16;
        int p = idx & 0xFFFF;
        int i = p >> 8;
        int j = p & 255;

        BParams pr = g_params[b];
        const float4* __restrict__ qimg = g_quad + b*SS;
        float d0 = __ldg(depth + b*SS + p);
        float qx = fmaf((float)PH1, pr.sxq, ((float)j * (256.0f/255.0f) - 128.0f) * d0);
        float qy = fmaf((float)PH1, pr.syq, ((float)i * (256.0f/255.0f) - 128.0f) * d0);
        float pz = fmaf((float)PH1, pr.sz, d0);
        int nst = valid ? trip_count(d0, pr.mind, pr.sz) : 0;

        // ray-constant coordinate motion signs
        float cx = pr.sxq * pz - qx * pr.sz;
        float cy = pr.syq * pz - qy * pr.sz;

        bool sh = false;
        #pragma unroll 1
        for (int s = PH1; s < nst; s++) {
            qx += pr.sxq; qy += pr.syq; pz += pr.sz;
            float rz = frcp(pz);
            float x = fmaf(qx, rz, 127.5f);
            float y = fmaf(qy, rz, 127.5f);
            if (bilinq(qimg, x, y) < pz) { sh = true; break; }
            bool xout = (cx > 0.0f) ? (x >= 255.0f) : ((cx < 0.0f) ? (x <= 0.0f) : false);
            bool yout = (cy > 0.0f) ? (y >= 255.0f) : ((cy < 0.0f) ? (y <= 0.0f) : false);
            if (xout && yout) break;   // frozen corner, sample >= pz, pz decreasing
        }
        if (valid) g_shadow[idx] = sh ? 1.0f : 0.0f;
    }
}

// ---------------- horizontal blur ----------------
__global__ void __launch_bounds__(256)
blurh_kernel() {
    __shared__ float row[256];
    int r = blockIdx.x;
    int j = threadIdx.x;
    int base = r * 256;
    row[j] = g_shadow[base + j];
    __syncthreads();
    float acc = 0.0f;
    #pragma unroll
    for (int k = 0; k < 7; k++) {
        int jj = j + k - 3;
        if (jj >= 0 && jj < 256)
            acc += GW[k] * row[jj];
    }
    g_blurh[base + j] = acc;
}

// ---------------- final: vertical blur + full shading ----------------
__global__ void __launch_bounds__(256)
final_kernel(const float* __restrict__ netA,
             const float* __restrict__ normal,
             float* __restrict__ out) {
    int idx = blockIdx.x * blockDim.x + threadIdx.x;
    int b = idx >> 16;
    int p = idx & 0xFFFF;
    int i = p >> 8;
    int j = p & 255;

    BParams pr = g_params[b];

    float ss = 0.0f;
    int base = b*SS + j;
    #pragma unroll
    for (int k = 0; k < 7; k++) {
        int ii = i + k - 3;
        if (ii >= 0 && ii < 256)
            ss += GW[k] * __ldg(&g_blurh[base + ii*256]);
    }
    float sf = fminf(fmaxf(1.0f - ss, 0.1f), 1.0f);

    int nb = b*3*SS + p;
    float nx = __ldg(normal + nb);
    float ny = __ldg(normal + nb + SS);
    float nz = __ldg(normal + nb + 2*SS);

    float cosq = nx*pr.ldx + ny*pr.ldy + nz*pr.ldz;
    float diffuse = fmaxf(cosq, 0.0f);
    float shading = pr.la + pr.lb * diffuse * sf;

    float cj = (-1.0f + (float)j * (2.0f/255.0f)) * TCONST;
    float ci = (-1.0f + (float)i * (2.0f/255.0f)) * TCONST;
    float vx = -cj, vy = -ci;
    float rn = frsq(fmaf(vx, vx, fmaf(vy, vy, 1.0f)));
    vx *= rn; vy *= rn; float vz = rn;

    float rx = 2.0f*cosq*nx - pr.ldx;
    float ry = 2.0f*cosq*ny - pr.ldy;
    float rz = 2.0f*cosq*nz - pr.ldz;
    float spec = fmaxf(vx*rx + vy*ry + vz*rz, 0.0f);
    float mask = (i >= 5 && i < 251 && j >= 5 && j < 251) ? 1.0f : 0.0f;
    spec = spec * ((cosq > 0.0f) ? 1.0f : 0.0f) * mask;
    float specc = fminf(fmaxf(spec, EPSV), 1.0f - EPSV);
    float spec_shading = fpow(specc, pr.salpha);
    float spec_term = pr.sstr * pr.lb * spec_shading;

    int ab = b*5*SS + p;
    int ob = b*3*SS + p;
    #pragma unroll
    for (int c = 0; c < 3; c++) {
        float a = ftanh(__ldg(netA + ab + c*SS));
        float alb = fpow(fmaf(a, 0.5f, 0.5f), 2.2f);
        float v = alb * shading + spec_term;
        out[ob + c*SS] = fpow(fmaxf(v, EPSV), INV_GAMMA);
    }
}

extern "C" void kernel_launch(void* const* d_in, const int* in_sizes, int n_in,
                              void* d_out, int out_size) {
    const float* netA   = (const float*)d_in[0];
    const float* netL   = (const float*)d_in[1];
    const float* normal = (const float*)d_in[2];
    const float* depth  = (const float*)d_in[3];
    const float* light  = (const float*)d_in[4];
    float* out = (float*)d_out;

    reset_kernel<<<1, 64>>>();
    qbuild_kernel<<<NPIX/256, 256>>>(depth);
    params_kernel<<<1, 32>>>(netL, light);
    shadow_p1_kernel<<<NPIX/256, 256>>>(depth);
    shadow_p2_kernel<<<2048, 256>>>(depth);
    blurh_kernel<<<BATCH*S, 256>>>();
    final_kernel<<<NPIX/256, 256>>>(netA, normal, out);
}

// round 10
// speedup vs baseline: 2.5878x; 1.0911x over previous
#include <cuda_runtime.h>
#include <math.h>

#define BATCH 32
#define S 256
#define SS (S*S)
#define NPIX (BATCH*SS)
#define PH1 8

#define TCONST 0.08748866352592400522f   // tan(5 deg)
#define EPSV 1e-7f
#define T_ALPHA 10.313708498984760f      // sqrt(128)-1
#define INV_GAMMA 0.45454545454545453f

__device__ __constant__ float GW[7] = {
    0.07015932906686f, 0.13107487759864f, 0.19071282296459f,
    0.21610594073983f, 0.19071282296459f, 0.13107487759864f, 0.07015932906686f
};

struct BParams {
    float ldx, ldy, ldz;
    float sxq, syq, sz;
    float la, lb;
    float salpha;
    float sstr;
    float mind;
    float pad;
};

__device__ BParams g_params[BATCH];
__device__ unsigned g_minbits[BATCH];
__device__ int g_count;
__device__ int g_surv[NPIX];
__device__ float g_shadow[NPIX];
__device__ float g_blurh[NPIX];
__device__ float4 g_quad[NPIX];          // 4 bilinear taps per texel, border-clamped

// ---------- fast math helpers ----------
__device__ __forceinline__ float fex2(float x){ float r; asm("ex2.approx.f32 %0,%1;":"=f"(r):"f"(x)); return r; }
__device__ __forceinline__ float flg2(float x){ float r; asm("lg2.approx.f32 %0,%1;":"=f"(r):"f"(x)); return r; }
__device__ __forceinline__ float frcp(float x){ float r; asm("rcp.approx.f32 %0,%1;":"=f"(r):"f"(x)); return r; }
__device__ __forceinline__ float frsq(float x){ float r; asm("rsqrt.approx.f32 %0,%1;":"=f"(r):"f"(x)); return r; }
__device__ __forceinline__ float fpow(float x, float y){ return fex2(y * flg2(x)); }
__device__ __forceinline__ float ftanh(float x){
    float ax = fabsf(x);
    float t = fex2(-2.8853900817779268f * ax);
    float r = (1.0f - t) * frcp(1.0f + t);
    return copysignf(r, x);
}

// ---------------- reset ----------------
__global__ void reset_kernel() {
    int t = threadIdx.x;
    if (t < BATCH) g_minbits[t] = 0x7f7fffffu;
    if (t == 0) g_count = 0;
}

// ---------------- build quad map + per-batch min (fused) ----------------
__global__ void __launch_bounds__(256)
qbuild_kernel(const float* __restrict__ depth) {
    __shared__ unsigned sm[256];
    int idx = blockIdx.x * blockDim.x + threadIdx.x;
    int b = idx >> 16;
    int p = idx & 0xFFFF;
    int y = p >> 8;
    int x = p & 255;
    const float* dimg = depth + b*SS;
    int x1 = min(x + 1, 255);
    int y1 = min(y + 1, 255);
    float v00 = __ldg(dimg + y*256 + x);
    float v01 = __ldg(dimg + y*256 + x1);
    float v10 = __ldg(dimg + y1*256 + x);
    float v11 = __ldg(dimg + y1*256 + x1);
    g_quad[idx] = make_float4(v00, v01, v10, v11);

    sm[threadIdx.x] = __float_as_uint(v00);
    __syncthreads();
    for (int o = 128; o > 0; o >>= 1) {
        if (threadIdx.x < o) sm[threadIdx.x] = min(sm[threadIdx.x], sm[threadIdx.x + o]);
        __syncthreads();
    }
    if (threadIdx.x == 0) atomicMin(&g_minbits[b], sm[0]);
}

// ---------------- per-batch scalar params ----------------
__global__ void params_kernel(const float* __restrict__ netL,
                              const float* __restrict__ light) {
    int b = threadIdx.x;
    if (b >= BATCH) return;
    float lx = light[b*2+0];
    float ly = light[b*2+1];
    float nrm = sqrtf(lx*lx + ly*ly + 1.0f);
    float ldx = lx / nrm, ldy = ly / nrm, ldz = 1.0f / nrm;
    BParams p;
    p.ldx = ldx; p.ldy = ldy; p.ldz = ldz;
    const float QS = 128.0f / TCONST;
    p.sxq = -ldx / (float)S * QS;
    p.syq = -ldy / (float)S * QS;
    p.sz  = -ldz / (float)S;
    p.la = tanhf(netL[b*6+1]) * 0.5f + 0.5f;
    p.lb = tanhf(netL[b*6+2]) * 0.5f + 0.5f;
    float sa = tanhf(netL[b*6+0]);
    float t  = (sa * 0.5f + 0.5f) * T_ALPHA + 1.0f;
    p.salpha = t * t;
    p.sstr = (tanhf(netL[b*6+5]) * 0.5f + 0.5f) * 0.5f;
    p.mind = __uint_as_float(g_minbits[b]) - 1e-6f;
    p.pad = 0.0f;
    g_params[b] = p;
}

__device__ __forceinline__ int trip_count(float d0, float mind, float sz) {
    float f = (mind - d0) / sz;
    return min(S, (int)f + 1);
}

// clamp coords, return quad index + weights
__device__ __forceinline__ int qaddr(float x, float y, float& wx, float& wy) {
    float xc = fminf(fmaxf(x, 0.0f), 255.0f);
    float yc = fminf(fmaxf(y, 0.0f), 255.0f);
    int x0 = (int)xc;
    int y0 = (int)yc;
    wx = xc - (float)x0;
    wy = yc - (float)y0;
    return y0*256 + x0;
}

__device__ __forceinline__ float qblend(float4 q, float wx, float wy) {
    float top = q.x + wx*(q.y - q.x);
    float bot = q.z + wx*(q.w - q.z);
    return top + wy*(bot - top);
}

// March 4 consecutive steps with 4 INDEPENDENT loads (MLP=4).
// Advances qx/qy/pz by 4 steps; returns true if any of the 4 samples shadows.
// lastx/lasty = coords of the 4th step (for frozen-corner test).
__device__ __forceinline__ bool march4(const float4* __restrict__ qimg,
                                       float& qx, float& qy, float& pz,
                                       float sxq, float syq, float sz,
                                       float& lastx, float& lasty) {
    float qx1 = qx + sxq,      qy1 = qy + syq,      pz1 = pz + sz;
    float qx2 = qx + 2.0f*sxq, qy2 = qy + 2.0f*syq, pz2 = pz + 2.0f*sz;
    float qx3 = qx + 3.0f*sxq, qy3 = qy + 3.0f*syq, pz3 = pz + 3.0f*sz;
    float qx4 = qx + 4.0f*sxq, qy4 = qy + 4.0f*syq, pz4 = pz + 4.0f*sz;
    float rz1 = frcp(pz1), rz2 = frcp(pz2), rz3 = frcp(pz3), rz4 = frcp(pz4);
    float x1 = fmaf(qx1, rz1, 127.5f), y1 = fmaf(qy1, rz1, 127.5f);
    float x2 = fmaf(qx2, rz2, 127.5f), y2 = fmaf(qy2, rz2, 127.5f);
    float x3 = fmaf(qx3, rz3, 127.5f), y3 = fmaf(qy3, rz3, 127.5f);
    float x4 = fmaf(qx4, rz4, 127.5f), y4 = fmaf(qy4, rz4, 127.5f);
    float wx1, wy1, wx2, wy2, wx3, wy3, wx4, wy4;
    int a1 = qaddr(x1, y1, wx1, wy1);
    int a2 = qaddr(x2, y2, wx2, wy2);
    int a3 = qaddr(x3, y3, wx3, wy3);
    int a4 = qaddr(x4, y4, wx4, wy4);
    float4 q1 = __ldg(qimg + a1);
    float4 q2 = __ldg(qimg + a2);
    float4 q3 = __ldg(qimg + a3);
    float4 q4 = __ldg(qimg + a4);
    bool sh = (qblend(q1, wx1, wy1) < pz1)
            | (qblend(q2, wx2, wy2) < pz2)
            | (qblend(q3, wx3, wy3) < pz3)
            | (qblend(q4, wx4, wy4) < pz4);
    qx = qx4; qy = qy4; pz = pz4;
    lastx = x4; lasty = y4;
    return sh;
}

// ---------------- shadow phase 1: 8 steps as 2 groups of 4 ----------------
__global__ void __launch_bounds__(256)
shadow_p1_kernel(const float* __restrict__ depth) {
    int idx = blockIdx.x * blockDim.x + threadIdx.x;
    int b = idx >> 16;
    int p = idx & 0xFFFF;
    int i = p >> 8;
    int j = p & 255;

    BParams pr = g_params[b];
    const float4* __restrict__ qimg = g_quad + b*SS;

    float d0 = __ldg(depth + b*SS + p);
    float qx = ((float)j * (256.0f/255.0f) - 128.0f) * d0;
    float qy = ((float)i * (256.0f/255.0f) - 128.0f) * d0;
    float pz = d0;
    int nst = trip_count(d0, pr.mind, pr.sz);

    float lx_, ly_;
    // group 1 (steps 1-4); overrun past nst is value-preserving (pz<=mind<sampled there)
    bool sh = march4(qimg, qx, qy, pz, pr.sxq, pr.syq, pr.sz, lx_, ly_);
    // group 2 (steps 5-8), only if not shadowed and ray still live
    if (!sh && nst > 4)
        sh = march4(qimg, qx, qy, pz, pr.sxq, pr.syq, pr.sz, lx_, ly_);

    bool alive = (!sh) && (nst > PH1);
    unsigned mask = __ballot_sync(0xFFFFFFFFu, alive);
    if (alive) {
        int lane = threadIdx.x & 31;
        int leader = __ffs(mask) - 1;
        int pos = 0;
        if (lane == leader) pos = atomicAdd(&g_count, __popc(mask));
        pos = __shfl_sync(0xFFFFFFFFu, pos, leader);
        g_surv[pos + __popc(mask & ((1u << lane) - 1u))] = idx;
    } else {
        g_shadow[idx] = sh ? 1.0f : 0.0f;
    }
}

// ---------------- shadow phase 2: dense survivors, groups of 4 ----------------
__global__ void __launch_bounds__(256)
shadow_p2_kernel(const float* __restrict__ depth) {
    int total = g_count;
    int lane = threadIdx.x & 31;
    int gwarp = (blockIdx.x * blockDim.x + threadIdx.x) >> 5;
    int nwarps = (gridDim.x * blockDim.x) >> 5;

    for (int base = gwarp * 32; base < total; base += nwarps * 32) {
        int k = base + lane;
        bool valid = (k < total);
        int idx = valid ? g_surv[k] : g_surv[total - 1];
        int b = idx >> 16;
        int p = idx & 0xFFFF;
        int i = p >> 8;
        int j = p & 255;

        BParams pr = g_params[b];
        const float4* __restrict__ qimg = g_quad + b*SS;
        float d0 = __ldg(depth + b*SS + p);
        float qx = fmaf((float)PH1, pr.sxq, ((float)j * (256.0f/255.0f) - 128.0f) * d0);
        float qy = fmaf((float)PH1, pr.syq, ((float)i * (256.0f/255.0f) - 128.0f) * d0);
        float pz = fmaf((float)PH1, pr.sz, d0);
        int nst = valid ? trip_count(d0, pr.mind, pr.sz) : 0;

        // ray-constant coordinate motion signs
        float cx = pr.sxq * pz - qx * pr.sz;
        float cy = pr.syq * pz - qy * pr.sz;

        bool sh = false;
        #pragma unroll 1
        for (int s = PH1; s < nst; s += 4) {
            float lx_, ly_;
            sh = march4(qimg, qx, qy, pz, pr.sxq, pr.syq, pr.sz, lx_, ly_);
            if (sh) break;
            // frozen-corner exit on group's last coord (coords monotone along ray)
            bool xout = (cx > 0.0f) ? (lx_ >= 255.0f) : ((cx < 0.0f) ? (lx_ <= 0.0f) : false);
            bool yout = (cy > 0.0f) ? (ly_ >= 255.0f) : ((cy < 0.0f) ? (ly_ <= 0.0f) : false);
            if (xout && yout) break;
        }
        if (valid) g_shadow[idx] = sh ? 1.0f : 0.0f;
    }
}

// ---------------- horizontal blur ----------------
__global__ void __launch_bounds__(256)
blurh_kernel() {
    __shared__ float row[256];
    int r = blockIdx.x;
    int j = threadIdx.x;
    int base = r * 256;
    row[j] = g_shadow[base + j];
    __syncthreads();
    float acc = 0.0f;
    #pragma unroll
    for (int k = 0; k < 7; k++) {
        int jj = j + k - 3;
        if (jj >= 0 && jj < 256)
            acc += GW[k] * row[jj];
    }
    g_blurh[base + j] = acc;
}

// ---------------- final: vertical blur + full shading ----------------
__global__ void __launch_bounds__(256)
final_kernel(const float* __restrict__ netA,
             const float* __restrict__ normal,
             float* __restrict__ out) {
    int idx = blockIdx.x * blockDim.x + threadIdx.x;
    int b = idx >> 16;
    int p = idx & 0xFFFF;
    int i = p >> 8;
    int j = p & 255;

    BParams pr = g_params[b];

    float ss = 0.0f;
    int base = b*SS + j;
    #pragma unroll
    for (int k = 0; k < 7; k++) {
        int ii = i + k - 3;
        if (ii >= 0 && ii < 256)
            ss += GW[k] * __ldg(&g_blurh[base + ii*256]);
    }
    float sf = fminf(fmaxf(1.0f - ss, 0.1f), 1.0f);

    int nb = b*3*SS + p;
    float nx = __ldg(normal + nb);
    float ny = __ldg(normal + nb + SS);
    float nz = __ldg(normal + nb + 2*SS);

    float cosq = nx*pr.ldx + ny*pr.ldy + nz*pr.ldz;
    float diffuse = fmaxf(cosq, 0.0f);
    float shading = pr.la + pr.lb * diffuse * sf;

    float cj = (-1.0f + (float)j * (2.0f/255.0f)) * TCONST;
    float ci = (-1.0f + (float)i * (2.0f/255.0f)) * TCONST;
    float vx = -cj, vy = -ci;
    float rn = frsq(fmaf(vx, vx, fmaf(vy, vy, 1.0f)));
    vx *= rn; vy *= rn; float vz = rn;

    float rx = 2.0f*cosq*nx - pr.ldx;
    float ry = 2.0f*cosq*ny - pr.ldy;
    float rz = 2.0f*cosq*nz - pr.ldz;
    float spec = fmaxf(vx*rx + vy*ry + vz*rz, 0.0f);
    float mask = (i >= 5 && i < 251 && j >= 5 && j < 251) ? 1.0f : 0.0f;
    spec = spec * ((cosq > 0.0f) ? 1.0f : 0.0f) * mask;
    float specc = fminf(fmaxf(spec, EPSV), 1.0f - EPSV);
    float spec_shading = fpow(specc, pr.salpha);
    float spec_term = pr.sstr * pr.lb * spec_shading;

    int ab = b*5*SS + p;
    int ob = b*3*SS + p;
    #pragma unroll
    for (int c = 0; c < 3; c++) {
        float a = ftanh(__ldg(netA + ab + c*SS));
        float alb = fpow(fmaf(a, 0.5f, 0.5f), 2.2f);
        float v = alb * shading + spec_term;
        out[ob + c*SS] = fpow(fmaxf(v, EPSV), INV_GAMMA);
    }
}

extern "C" void kernel_launch(void* const* d_in, const int* in_sizes, int n_in,
                              void* d_out, int out_size) {
    const float* netA   = (const float*)d_in[0];
    const float* netL   = (const float*)d_in[1];
    const float* normal = (const float*)d_in[2];
    const float* depth  = (const float*)d_in[3];
    const float* light  = (const float*)d_in[4];
    float* out = (float*)d_out;

    reset_kernel<<<1, 64>>>();
    qbuild_kernel<<<NPIX/256, 256>>>(depth);
    params_kernel<<<1, 32>>>(netL, light);
    shadow_p1_kernel<<<NPIX/256, 256>>>(depth);
    shadow_p2_kernel<<<2048, 256>>>(depth);
    blurh_kernel<<<BATCH*S, 256>>>();
    final_kernel<<<NPIX/256, 256>>>(netA, normal, out);
}